// round 16
// baseline (speedup 1.0000x reference)
#include <cuda_runtime.h>
#include <cuda_bf16.h>
#include <stdint.h>

#define NTILES 4352          // 139264 / 32 points
#define TEQ    4096
#define TIB    4224
#define NU     0.0031830988618379067154f
typedef unsigned long long u64;

__device__ uint2 g_wfH[12288];
__device__ uint2 g_wfL[12288];

__device__ __forceinline__ uint32_t pkbf(float lo, float hi) {
    uint32_t r; asm("cvt.rn.bf16x2.f32 %0, %1, %2;" : "=r"(r) : "f"(hi), "f"(lo)); return r;
}
__device__ __forceinline__ void split2(float v0, float v1, uint32_t& h, uint32_t& l) {
    h = pkbf(v0, v1);
    float h0 = __uint_as_float(h << 16);
    float h1 = __uint_as_float(h & 0xffff0000u);
    l = pkbf(v0 - h0, v1 - h1);
}
__device__ __forceinline__ u64 pk2(float lo, float hi) {
    u64 r; asm("mov.b64 %0, {%1, %2};" : "=l"(r) : "f"(lo), "f"(hi)); return r;
}
__device__ __forceinline__ void upk2(u64 v, float& lo, float& hi) {
    asm("mov.b64 {%0, %1}, %2;" : "=f"(lo), "=f"(hi) : "l"(v));
}
__device__ __forceinline__ void fma2(u64& d, u64 a, u64 b) {
    asm("fma.rn.f32x2 %0, %1, %2, %0;" : "+l"(d) : "l"(a), "l"(b));
}
__device__ __forceinline__ u64 mul2(u64 a, u64 b) {
    u64 r; asm("mul.rn.f32x2 %0, %1, %2;" : "=l"(r) : "l"(a), "l"(b)); return r;
}
__device__ __forceinline__ float tanhf_fast(float z) {
    float e = __expf(2.0f * z);
    return __fdividef(e - 1.0f, e + 1.0f);
}
__device__ __forceinline__ void mma16816(float* c, const uint32_t* a, uint32_t b0, uint32_t b1) {
    asm volatile(
        "mma.sync.aligned.m16n8k16.row.col.f32.bf16.bf16.f32 "
        "{%0,%1,%2,%3}, {%4,%5,%6,%7}, {%8,%9}, {%0,%1,%2,%3};"
        : "+f"(c[0]), "+f"(c[1]), "+f"(c[2]), "+f"(c[3])
        : "r"(a[0]), "r"(a[1]), "r"(a[2]), "r"(a[3]), "r"(b0), "r"(b1));
}

__global__ void prep_kernel(const float* __restrict__ W1,
                            const float* __restrict__ W2,
                            const float* __restrict__ W3)
{
    const int gt = blockIdx.x * blockDim.x + threadIdx.x;
    const int lane = gt & 31, wi = gt >> 5;
    const int nt = wi & 15, ks = (wi >> 4) & 7, l = wi >> 7;
    const float* W = (l == 0) ? W1 : (l == 1) ? W2 : W3;
    const int j = nt * 8 + (lane >> 2), k0 = ks * 16 + 2 * (lane & 3);
    uint32_t h0, l0, h1, l1;
    split2(W[k0 * 128 + j], W[(k0 + 1) * 128 + j], h0, l0);
    split2(W[(k0 + 8) * 128 + j], W[(k0 + 9) * 128 + j], h1, l1);
    g_wfH[wi * 32 + lane] = make_uint2(h0, h1);
    g_wfL[wi * 32 + lane] = make_uint2(l0, l1);
}

// smem: whS 98304 | st0 16896 | st1T [128][36]f 18432 | st2 16896 | st3 16896 | st4 16896
#define OFF_ST0  98304
#define OFF_ST1T 115200
#define OFF_ST2  133632
#define OFF_ST3  150528
#define OFF_ST4  167424
#define SMEM_BYTES 184320

extern __shared__ char smem_raw[];

__global__ __launch_bounds__(512, 1)
void pinn_mma(const float* __restrict__ tx_eq, const float* __restrict__ tx_init,
              const float* __restrict__ tx_bnd,
              const float* __restrict__ W0, const float* __restrict__ b0,
              const float* __restrict__ W1, const float* __restrict__ b1,
              const float* __restrict__ W2, const float* __restrict__ b2,
              const float* __restrict__ W3, const float* __restrict__ b3,
              const float* __restrict__ W4, const float* __restrict__ b4,
              float* __restrict__ out)
{
    uint2* whS  = (uint2*)smem_raw;
    float* st0  = (float*)(smem_raw + OFF_ST0);   // a      [32][132]
    float* st1T = (float*)(smem_raw + OFF_ST1T);  // at     [128][36] transposed
    float* st2  = (float*)(smem_raw + OFF_ST2);   // raw zx [32][132]
    float* st3  = (float*)(smem_raw + OFF_ST3);   // axx    [32][132]
    float* st4  = (float*)(smem_raw + OFF_ST4);   // ax     [32][132]

    const int tid  = threadIdx.x;
    const int lane = tid & 31;
    const int wid  = tid >> 5;            // 0..15
    const int sub  = wid >> 2;            // 0..3
    const int s    = (sub + wid) & 3;     // state, one of each per SMSP
    const int R    = sub & 1;
    const int nh   = sub >> 1;
    const int q    = lane & 3;
    const int ra   = 16 * R + (lane >> 2);
    const int rb   = ra + 8;
    const bool isT = (s != 1);            // tensor warp?

    float* stS = (s == 0) ? st0 : (s == 2) ? st4 : st3;   // tensor A source

    for (int i = tid; i < 12288; i += 512) whS[i] = g_wfH[i];
    const float b4v = __ldg(b4);
    __syncthreads();

    for (int tile = blockIdx.x; tile < NTILES; tile += gridDim.x) {
        const float2* src;
        if (tile < TEQ)      src = (const float2*)tx_eq  + tile * 32;
        else if (tile < TIB) src = (const float2*)tx_init + (tile - TEQ) * 32;
        else                 src = (const float2*)tx_bnd  + (tile - TIB) * 32;

        // ---- layer 0 seeds (all threads, all buffers) ----
        for (int idx = tid; idx < 2048; idx += 512) {
            const int pt = idx >> 6, jp = idx & 63;
            const float2 P = __ldg(src + pt);
            float av[2], tv[2], xv[2], xxv[2];
            #pragma unroll
            for (int m = 0; m < 2; m++) {
                const int j = 2 * jp + m;
                const float wt = __ldg(W0 + j);
                const float wx = __ldg(W0 + 128 + j);
                const float bb = __ldg(b0 + j);
                const float z = fmaf(wt, P.x, fmaf(wx, P.y, bb));
                const float a = tanhf_fast(z);
                const float p = 1.0f - a * a;
                av[m] = a; tv[m] = p * wt; xv[m] = p * wx;
                xxv[m] = -2.0f * a * xv[m] * wx;
            }
            *(float2*)(st0 + pt * 132 + 2 * jp) = make_float2(av[0], av[1]);
            *(float2*)(st4 + pt * 132 + 2 * jp) = make_float2(xv[0], xv[1]);
            *(float2*)(st3 + pt * 132 + 2 * jp) = make_float2(xxv[0], xxv[1]);
            st1T[(2 * jp)     * 36 + pt] = tv[0];
            st1T[(2 * jp + 1) * 36 + pt] = tv[1];
        }
        __syncthreads();

        // ---- 3 hidden layers ----
        #pragma unroll 1
        for (int l = 0; l < 3; l++) {
            const float* Wl = (l == 0) ? W1 : (l == 1) ? W2 : W3;
            float c[8][4];
            u64 acc[2][8];
            if (isT) {
                // tensor: 3-term bf16 split, K 0..127
                #pragma unroll
                for (int nt = 0; nt < 8; nt++) {
                    c[nt][0] = 0.f; c[nt][1] = 0.f; c[nt][2] = 0.f; c[nt][3] = 0.f;
                }
                const uint2* bh  = whS + l * 4096 + lane;
                const uint2* blg = g_wfL + l * 4096 + lane;
                #pragma unroll
                for (int ks = 0; ks < 8; ks++) {
                    uint2 BL[8], BH[8];
                    #pragma unroll
                    for (int nt = 0; nt < 8; nt++)
                        BL[nt] = __ldg(blg + (ks * 16 + 8 * nh + nt) * 32);
                    #pragma unroll
                    for (int nt = 0; nt < 8; nt++)
                        BH[nt] = bh[(ks * 16 + 8 * nh + nt) * 32];
                    const float2 v0 = *(const float2*)(stS + ra * 132 + 16 * ks + 2 * q);
                    const float2 v1 = *(const float2*)(stS + rb * 132 + 16 * ks + 2 * q);
                    const float2 v2 = *(const float2*)(stS + ra * 132 + 16 * ks + 8 + 2 * q);
                    const float2 v3 = *(const float2*)(stS + rb * 132 + 16 * ks + 8 + 2 * q);
                    uint32_t aH[4], aL[4];
                    split2(v0.x, v0.y, aH[0], aL[0]);
                    split2(v1.x, v1.y, aH[1], aL[1]);
                    split2(v2.x, v2.y, aH[2], aL[2]);
                    split2(v3.x, v3.y, aH[3], aL[3]);
                    #pragma unroll
                    for (int nt = 0; nt < 8; nt++) mma16816(c[nt], aH, BH[nt].x, BH[nt].y);
                    #pragma unroll
                    for (int nt = 0; nt < 8; nt++) mma16816(c[nt], aL, BH[nt].x, BH[nt].y);
                    #pragma unroll
                    for (int nt = 0; nt < 8; nt++) mma16816(c[nt], aH, BL[nt].x, BL[nt].y);
                }
            } else {
                // SIMT t-state: exact fp32, 16 pts x 2 cols per lane
                #pragma unroll
                for (int cc = 0; cc < 2; cc++)
                    #pragma unroll
                    for (int pp = 0; pp < 8; pp++) acc[cc][pp] = 0ull;
                const int n0 = 64 * nh + 2 * lane;
                #pragma unroll 4
                for (int k = 0; k < 128; k++) {
                    const float2 wv = __ldg((const float2*)(Wl + k * 128 + n0));
                    const u64 w0 = pk2(wv.x, wv.x);
                    const u64 w1 = pk2(wv.y, wv.y);
                    const u64* rp = (const u64*)(st1T + k * 36 + 16 * R);
                    const ulonglong2 u0 = *(const ulonglong2*)(rp);
                    const ulonglong2 u1 = *(const ulonglong2*)(rp + 2);
                    const ulonglong2 u2 = *(const ulonglong2*)(rp + 4);
                    const ulonglong2 u3 = *(const ulonglong2*)(rp + 6);
                    const u64 v_[8] = { u0.x, u0.y, u1.x, u1.y, u2.x, u2.y, u3.x, u3.y };
                    #pragma unroll
                    for (int pp = 0; pp < 8; pp++) {
                        fma2(acc[0][pp], w0, v_[pp]);
                        fma2(acc[1][pp], w1, v_[pp]);
                    }
                }
            }
            __syncthreads();   // all reads of state buffers done before rewrites

            const float* bb = (l == 0) ? b1 : (l == 1) ? b2 : b3;
            // phase A: a-warps activate + publish; x-warps publish raw zx
            if (s == 0) {
                #pragma unroll
                for (int nt = 0; nt < 8; nt++) {
                    const int col0 = 64 * nh + 8 * nt + 2 * q;
                    const float bv0 = __ldg(bb + col0);
                    const float bv1 = __ldg(bb + col0 + 1);
                    const float a00 = tanhf_fast(c[nt][0] + bv0);
                    const float a01 = tanhf_fast(c[nt][1] + bv1);
                    const float a10 = tanhf_fast(c[nt][2] + bv0);
                    const float a11 = tanhf_fast(c[nt][3] + bv1);
                    *(float2*)(st0 + ra * 132 + col0) = make_float2(a00, a01);
                    *(float2*)(st0 + rb * 132 + col0) = make_float2(a10, a11);
                }
            } else if (s == 2) {
                #pragma unroll
                for (int nt = 0; nt < 8; nt++) {
                    const int col0 = 64 * nh + 8 * nt + 2 * q;
                    *(float2*)(st2 + ra * 132 + col0) = make_float2(c[nt][0], c[nt][1]);
                    *(float2*)(st2 + rb * 132 + col0) = make_float2(c[nt][2], c[nt][3]);
                }
            }
            __syncthreads();
            // phase B: derivative couplings
            if (s == 2 || s == 3) {
                #pragma unroll
                for (int nt = 0; nt < 8; nt++) {
                    const int col0 = 64 * nh + 8 * nt + 2 * q;
                    const float2 aA = *(const float2*)(st0 + ra * 132 + col0);
                    const float2 aB = *(const float2*)(st0 + rb * 132 + col0);
                    const float p00 = 1.0f - aA.x * aA.x, p01 = 1.0f - aA.y * aA.y;
                    const float p10 = 1.0f - aB.x * aB.x, p11 = 1.0f - aB.y * aB.y;
                    float o0, o1, o2, o3;
                    if (s == 3) {
                        const float2 xA = *(const float2*)(st2 + ra * 132 + col0);
                        const float2 xB = *(const float2*)(st2 + rb * 132 + col0);
                        o0 = p00 * fmaf(-2.0f * aA.x * xA.x, xA.x, c[nt][0]);
                        o1 = p01 * fmaf(-2.0f * aA.y * xA.y, xA.y, c[nt][1]);
                        o2 = p10 * fmaf(-2.0f * aB.x * xB.x, xB.x, c[nt][2]);
                        o3 = p11 * fmaf(-2.0f * aB.y * xB.y, xB.y, c[nt][3]);
                    } else {
                        o0 = p00 * c[nt][0]; o1 = p01 * c[nt][1];
                        o2 = p10 * c[nt][2]; o3 = p11 * c[nt][3];
                    }
                    float* dst = (s == 2) ? st4 : st3;
                    *(float2*)(dst + ra * 132 + col0) = make_float2(o0, o1);
                    *(float2*)(dst + rb * 132 + col0) = make_float2(o2, o3);
                }
            } else if (s == 1) {
                const int n0 = 64 * nh + 2 * lane;
                #pragma unroll
                for (int pp = 0; pp < 8; pp++) {
                    const int pt0 = 16 * R + 2 * pp;
                    const float a00 = st0[pt0 * 132 + n0];
                    const float a01 = st0[pt0 * 132 + n0 + 1];
                    const float a10 = st0[(pt0 + 1) * 132 + n0];
                    const float a11 = st0[(pt0 + 1) * 132 + n0 + 1];
                    const u64 p0 = pk2(1.0f - a00 * a00, 1.0f - a10 * a10);
                    const u64 p1 = pk2(1.0f - a01 * a01, 1.0f - a11 * a11);
                    const u64 o0 = mul2(p0, acc[0][pp]);
                    const u64 o1 = mul2(p1, acc[1][pp]);
                    float f0, f1;
                    upk2(o0, f0, f1);
                    *(float2*)(st1T + n0 * 36 + pt0) = make_float2(f0, f1);
                    upk2(o1, f0, f1);
                    *(float2*)(st1T + (n0 + 1) * 36 + pt0) = make_float2(f0, f1);
                }
            }
            __syncthreads();
        }

        // ---- layer 4: warp wid reduces rows 2wid, 2wid+1 over all states ----
        {
            float acc4[2][4];
            #pragma unroll
            for (int r = 0; r < 2; r++)
                #pragma unroll
                for (int k = 0; k < 4; k++) acc4[r][k] = 0.f;
            #pragma unroll
            for (int m = 0; m < 4; m++) {
                const int j = lane + 32 * m;
                const float w4 = __ldg(W4 + j);
                #pragma unroll
                for (int r = 0; r < 2; r++) {
                    const int row = 2 * wid + r;
                    acc4[r][0] = fmaf(w4, st0[row * 132 + j], acc4[r][0]);
                    acc4[r][1] = fmaf(w4, st1T[j * 36 + row], acc4[r][1]);
                    acc4[r][2] = fmaf(w4, st4[row * 132 + j], acc4[r][2]);
                    acc4[r][3] = fmaf(w4, st3[row * 132 + j], acc4[r][3]);
                }
            }
            #pragma unroll
            for (int off = 16; off > 0; off >>= 1)
                #pragma unroll
                for (int r = 0; r < 2; r++)
                    #pragma unroll
                    for (int k = 0; k < 4; k++)
                        acc4[r][k] += __shfl_down_sync(0xffffffffu, acc4[r][k], off);
            if (lane == 0) {
                #pragma unroll
                for (int r = 0; r < 2; r++) {
                    const float u   = acc4[r][0] + b4v;
                    const float ut  = acc4[r][1];
                    const float ux  = acc4[r][2];
                    const float uxx = acc4[r][3];
                    out[tile * 32 + 2 * wid + r] =
                        (tile < TEQ) ? (fmaf(u, ux, ut) - NU * uxx) : u;
                }
            }
        }
        __syncthreads();
    }
}

extern "C" void kernel_launch(void* const* d_in, const int* in_sizes, int n_in,
                              void* d_out, int out_size)
{
    const float* tx_eq   = (const float*)d_in[0];
    const float* tx_init = (const float*)d_in[1];
    const float* tx_bnd  = (const float*)d_in[2];
    const float* W0 = (const float*)d_in[3];
    const float* b0 = (const float*)d_in[4];
    const float* W1 = (const float*)d_in[5];
    const float* b1 = (const float*)d_in[6];
    const float* W2 = (const float*)d_in[7];
    const float* b2 = (const float*)d_in[8];
    const float* W3 = (const float*)d_in[9];
    const float* b3 = (const float*)d_in[10];
    const float* W4 = (const float*)d_in[11];
    const float* b4 = (const float*)d_in[12];
    float* out = (float*)d_out;

    prep_kernel<<<48, 256>>>(W1, W2, W3);

    cudaFuncSetAttribute(pinn_mma, cudaFuncAttributeMaxDynamicSharedMemorySize, SMEM_BYTES);
    int sms = 148;
    cudaDeviceGetAttribute(&sms, cudaDevAttrMultiProcessorCount, 0);
    if (sms > NTILES) sms = NTILES;

    pinn_mma<<<sms, 512, SMEM_BYTES>>>(tx_eq, tx_init, tx_bnd,
        W0, b0, W1, b1, W2, b2, W3, b3, W4, b4, out);
}

// round 17
// speedup vs baseline: 1.2776x; 1.2776x over previous
#include <cuda_runtime.h>
#include <cuda_bf16.h>
#include <stdint.h>

#define NTILES 4352          // 139264 / 32 points
#define TEQ    4096
#define TIB    4224
#define NU     0.0031830988618379067154f

// bf16 high-part B fragments: [l][ks(8)][nt(16)][lane] -> uint2
__device__ uint2 g_wfH[12288];
// fp8 correction B fragments: [l][ksc(4)][nt(16)][lane] -> uint2 {b0,b1}
__device__ uint2 g_w8h[6144];   // e4m3(wh)
__device__ uint2 g_w8l[6144];   // e4m3(wl * 512)

__device__ __forceinline__ uint32_t pkbf(float lo, float hi) {
    uint32_t r; asm("cvt.rn.bf16x2.f32 %0, %1, %2;" : "=r"(r) : "f"(hi), "f"(lo)); return r;
}
__device__ __forceinline__ float bf16f(float v) {
    return __bfloat162float(__float2bfloat16(v));
}
__device__ __forceinline__ uint32_t pk_e4m3(float f0, float f1, float f2, float f3) {
    uint32_t r;
    asm("{\n\t.reg .b16 lo, hi;\n\t"
        "cvt.rn.satfinite.e4m3x2.f32 lo, %2, %1;\n\t"
        "cvt.rn.satfinite.e4m3x2.f32 hi, %4, %3;\n\t"
        "mov.b32 %0, {lo, hi};\n\t}"
        : "=r"(r) : "f"(f0), "f"(f1), "f"(f2), "f"(f3));
    return r;
}
__device__ __forceinline__ float tanhf_fast(float z) {
    float e = __expf(2.0f * z);
    return __fdividef(e - 1.0f, e + 1.0f);
}
__device__ __forceinline__ void mma16816(float* c, const uint32_t* a, uint32_t b0, uint32_t b1) {
    asm volatile(
        "mma.sync.aligned.m16n8k16.row.col.f32.bf16.bf16.f32 "
        "{%0,%1,%2,%3}, {%4,%5,%6,%7}, {%8,%9}, {%0,%1,%2,%3};"
        : "+f"(c[0]), "+f"(c[1]), "+f"(c[2]), "+f"(c[3])
        : "r"(a[0]), "r"(a[1]), "r"(a[2]), "r"(a[3]), "r"(b0), "r"(b1));
}
__device__ __forceinline__ void mma_fp8(float* c, const uint32_t* a, uint32_t b0, uint32_t b1) {
    asm volatile(
        "mma.sync.aligned.m16n8k32.row.col.f32.e4m3.e4m3.f32 "
        "{%0,%1,%2,%3}, {%4,%5,%6,%7}, {%8,%9}, {%0,%1,%2,%3};"
        : "+f"(c[0]), "+f"(c[1]), "+f"(c[2]), "+f"(c[3])
        : "r"(a[0]), "r"(a[1]), "r"(a[2]), "r"(a[3]), "r"(b0), "r"(b1));
}

__global__ void prep_kernel(const float* __restrict__ W1,
                            const float* __restrict__ W2,
                            const float* __restrict__ W3)
{
    const int gt = blockIdx.x * blockDim.x + threadIdx.x;   // 0..12287
    const int lane = gt & 31;
    // bf16 high fragments (all 12288 threads)
    {
        const int wi = gt >> 5;
        const int nt = wi & 15, ks = (wi >> 4) & 7, l = wi >> 7;
        const float* W = (l == 0) ? W1 : (l == 1) ? W2 : W3;
        const int j = nt * 8 + (lane >> 2), k0 = ks * 16 + 2 * (lane & 3);
        g_wfH[gt] = make_uint2(
            pkbf(bf16f(W[k0 * 128 + j]),       bf16f(W[(k0 + 1) * 128 + j])),
            pkbf(bf16f(W[(k0 + 8) * 128 + j]), bf16f(W[(k0 + 9) * 128 + j])));
    }
    // fp8 correction fragments (first 6144 threads)
    if (gt < 6144) {
        const int wi = gt >> 5;
        const int nt = wi & 15, ksc = (wi >> 4) & 3, l = wi >> 6;
        const float* W = (l == 0) ? W1 : (l == 1) ? W2 : W3;
        const int j = nt * 8 + (lane >> 2);
        const int kb = ksc * 32 + 4 * (lane & 3);
        float wh[8], wl[8];
        #pragma unroll
        for (int i = 0; i < 4; i++) {
            const float w0 = W[(kb + i) * 128 + j];
            const float w1 = W[(kb + 16 + i) * 128 + j];
            wh[i]     = bf16f(w0); wl[i]     = (w0 - wh[i]) * 512.0f;
            wh[4 + i] = bf16f(w1); wl[4 + i] = (w1 - wh[4 + i]) * 512.0f;
        }
        g_w8h[gt] = make_uint2(pk_e4m3(wh[0], wh[1], wh[2], wh[3]),
                               pk_e4m3(wh[4], wh[5], wh[6], wh[7]));
        g_w8l[gt] = make_uint2(pk_e4m3(wl[0], wl[1], wl[2], wl[3]),
                               pk_e4m3(wl[4], wl[5], wl[6], wl[7]));
    }
}

// smem: whS 98304 | 5 state buffers of 32 x 132 floats (16896 B each)
#define ST_STRIDE 132
#define ST_FLOATS 4224
#define SMEM_BYTES (98304 + 5 * 16896)   // 182784

extern __shared__ char smem_raw[];

__global__ __launch_bounds__(512, 1)
void pinn_mma(const float* __restrict__ tx_eq, const float* __restrict__ tx_init,
              const float* __restrict__ tx_bnd,
              const float* __restrict__ W0, const float* __restrict__ b0,
              const float* __restrict__ b1, const float* __restrict__ b2,
              const float* __restrict__ b3,
              const float* __restrict__ W4, const float* __restrict__ b4,
              float* __restrict__ out)
{
    uint2* whS = (uint2*)smem_raw;
    float* stf = (float*)(smem_raw + 98304);
    float* st0 = stf;                  // a
    float* st1 = stf + ST_FLOATS;      // at
    float* st2 = stf + 2 * ST_FLOATS;  // raw zx scratch
    float* st3 = stf + 3 * ST_FLOATS;  // axx
    float* st4 = stf + 4 * ST_FLOATS;  // ax

    const int tid  = threadIdx.x;
    const int lane = tid & 31;
    const int wid  = tid >> 5;        // 0..15
    const int R    = wid & 1;
    const int s    = (wid >> 1) & 3;  // state
    const int nh   = wid >> 3;        // N-half
    const int q    = lane & 3;
    const int ra   = 16 * R + (lane >> 2);
    const int rb   = ra + 8;

    float* stS = (s == 0) ? st0 : (s == 1) ? st1 : (s == 2) ? st4 : st3;

    for (int i = tid; i < 12288; i += 512) whS[i] = g_wfH[i];
    const float b4v = __ldg(b4);
    __syncthreads();

    for (int tile = blockIdx.x; tile < NTILES; tile += gridDim.x) {
        const float2* src;
        if (tile < TEQ)      src = (const float2*)tx_eq  + tile * 32;
        else if (tile < TIB) src = (const float2*)tx_init + (tile - TEQ) * 32;
        else                 src = (const float2*)tx_bnd  + (tile - TIB) * 32;

        const float2 Pa = __ldg(src + ra);
        const float2 Pb = __ldg(src + rb);

        // ---- layer 0 seeds: each warp its state, its rows/cols ----
        #pragma unroll
        for (int nt = 0; nt < 8; nt++) {
            float vA[2], vB[2];
            #pragma unroll
            for (int m = 0; m < 2; m++) {
                const int col = 64 * nh + 8 * nt + 2 * q + m;
                const float wt = __ldg(W0 + col);
                const float wx = __ldg(W0 + 128 + col);
                const float bb = __ldg(b0 + col);
                const float za = fmaf(wt, Pa.x, fmaf(wx, Pa.y, bb));
                const float zb = fmaf(wt, Pb.x, fmaf(wx, Pb.y, bb));
                const float a0 = tanhf_fast(za), a1 = tanhf_fast(zb);
                const float p0 = 1.0f - a0 * a0, p1 = 1.0f - a1 * a1;
                if (s == 0)      { vA[m] = a0;       vB[m] = a1; }
                else if (s == 1) { vA[m] = p0 * wt;  vB[m] = p1 * wt; }
                else if (s == 2) { vA[m] = p0 * wx;  vB[m] = p1 * wx; }
                else             { vA[m] = -2.0f * a0 * p0 * wx * wx;
                                   vB[m] = -2.0f * a1 * p1 * wx * wx; }
            }
            const int col0 = 64 * nh + 8 * nt + 2 * q;
            *(float2*)(stS + ra * ST_STRIDE + col0) = make_float2(vA[0], vA[1]);
            *(float2*)(stS + rb * ST_STRIDE + col0) = make_float2(vB[0], vB[1]);
        }
        __syncthreads();

        // ---- 3 hidden layers ----
        #pragma unroll 1
        for (int l = 0; l < 3; l++) {
            float c[8][4];
            #pragma unroll
            for (int nt = 0; nt < 8; nt++) {
                c[nt][0] = 0.f; c[nt][1] = 0.f; c[nt][2] = 0.f; c[nt][3] = 0.f;
            }

            // === fp8 corrections (values are 512x true) ===
            #pragma unroll
            for (int ksc = 0; ksc < 4; ksc++) {
                const int kb = 32 * ksc + 4 * q;
                float v[4][4];   // [frag 0:ra 1:rb 2:ra+16k 3:rb+16k][4 k-values]
                *(float2*)&v[0][0] = *(const float2*)(stS + ra * ST_STRIDE + kb);
                *(float2*)&v[0][2] = *(const float2*)(stS + ra * ST_STRIDE + kb + 2);
                *(float2*)&v[1][0] = *(const float2*)(stS + rb * ST_STRIDE + kb);
                *(float2*)&v[1][2] = *(const float2*)(stS + rb * ST_STRIDE + kb + 2);
                *(float2*)&v[2][0] = *(const float2*)(stS + ra * ST_STRIDE + kb + 16);
                *(float2*)&v[2][2] = *(const float2*)(stS + ra * ST_STRIDE + kb + 18);
                *(float2*)&v[3][0] = *(const float2*)(stS + rb * ST_STRIDE + kb + 16);
                *(float2*)&v[3][2] = *(const float2*)(stS + rb * ST_STRIDE + kb + 18);
                uint32_t A8h[4], A8l[4];
                #pragma unroll
                for (int f = 0; f < 4; f++) {
                    float ah[4], al[4];
                    #pragma unroll
                    for (int i = 0; i < 4; i++) {
                        ah[i] = bf16f(v[f][i]);
                        al[i] = (v[f][i] - ah[i]) * 512.0f;
                    }
                    A8h[f] = pk_e4m3(ah[0], ah[1], ah[2], ah[3]);
                    A8l[f] = pk_e4m3(al[0], al[1], al[2], al[3]);
                }
                const int base = ((l * 4 + ksc) * 16 + 8 * nh) * 32 + lane;
                #pragma unroll
                for (int nt = 0; nt < 8; nt++) {
                    const uint2 Bh = __ldg(g_w8h + base + nt * 32);
                    mma_fp8(c[nt], A8l, Bh.x, Bh.y);
                    const uint2 Bl = __ldg(g_w8l + base + nt * 32);
                    mma_fp8(c[nt], A8h, Bl.x, Bl.y);
                }
            }
            // scale corrections down
            #pragma unroll
            for (int nt = 0; nt < 8; nt++) {
                c[nt][0] *= 0.001953125f; c[nt][1] *= 0.001953125f;
                c[nt][2] *= 0.001953125f; c[nt][3] *= 0.001953125f;
            }

            // === bf16 hh term ===
            const uint2* bh = whS + l * 4096 + lane;
            #pragma unroll
            for (int ks = 0; ks < 8; ks++) {
                uint2 BH[8];
                #pragma unroll
                for (int nt = 0; nt < 8; nt++)
                    BH[nt] = bh[(ks * 16 + 8 * nh + nt) * 32];
                const float2 v0 = *(const float2*)(stS + ra * ST_STRIDE + 16 * ks + 2 * q);
                const float2 v1 = *(const float2*)(stS + rb * ST_STRIDE + 16 * ks + 2 * q);
                const float2 v2 = *(const float2*)(stS + ra * ST_STRIDE + 16 * ks + 8 + 2 * q);
                const float2 v3 = *(const float2*)(stS + rb * ST_STRIDE + 16 * ks + 8 + 2 * q);
                uint32_t aH[4];
                aH[0] = pkbf(v0.x, v0.y);
                aH[1] = pkbf(v1.x, v1.y);
                aH[2] = pkbf(v2.x, v2.y);
                aH[3] = pkbf(v3.x, v3.y);
                #pragma unroll
                for (int nt = 0; nt < 8; nt++)
                    mma16816(c[nt], aH, BH[nt].x, BH[nt].y);
            }
            __syncthreads();   // all reads of state buffers done before rewrites

            const float* bb = (l == 0) ? b1 : (l == 1) ? b2 : b3;
            // phase A: s0 activates + publishes a; s2 publishes raw zx
            if (s == 0) {
                #pragma unroll
                for (int nt = 0; nt < 8; nt++) {
                    const int col0 = 64 * nh + 8 * nt + 2 * q;
                    const float bv0 = __ldg(bb + col0);
                    const float bv1 = __ldg(bb + col0 + 1);
                    const float a00 = tanhf_fast(c[nt][0] + bv0);
                    const float a01 = tanhf_fast(c[nt][1] + bv1);
                    const float a10 = tanhf_fast(c[nt][2] + bv0);
                    const float a11 = tanhf_fast(c[nt][3] + bv1);
                    *(float2*)(st0 + ra * ST_STRIDE + col0) = make_float2(a00, a01);
                    *(float2*)(st0 + rb * ST_STRIDE + col0) = make_float2(a10, a11);
                }
            } else if (s == 2) {
                #pragma unroll
                for (int nt = 0; nt < 8; nt++) {
                    const int col0 = 64 * nh + 8 * nt + 2 * q;
                    *(float2*)(st2 + ra * ST_STRIDE + col0) = make_float2(c[nt][0], c[nt][1]);
                    *(float2*)(st2 + rb * ST_STRIDE + col0) = make_float2(c[nt][2], c[nt][3]);
                }
            }
            __syncthreads();
            // phase B: derivative couplings
            if (s != 0) {
                #pragma unroll
                for (int nt = 0; nt < 8; nt++) {
                    const int col0 = 64 * nh + 8 * nt + 2 * q;
                    const float2 aA = *(const float2*)(st0 + ra * ST_STRIDE + col0);
                    const float2 aB = *(const float2*)(st0 + rb * ST_STRIDE + col0);
                    const float p00 = 1.0f - aA.x * aA.x, p01 = 1.0f - aA.y * aA.y;
                    const float p10 = 1.0f - aB.x * aB.x, p11 = 1.0f - aB.y * aB.y;
                    float o0, o1, o2, o3;
                    if (s == 3) {
                        const float2 xA = *(const float2*)(st2 + ra * ST_STRIDE + col0);
                        const float2 xB = *(const float2*)(st2 + rb * ST_STRIDE + col0);
                        o0 = p00 * fmaf(-2.0f * aA.x * xA.x, xA.x, c[nt][0]);
                        o1 = p01 * fmaf(-2.0f * aA.y * xA.y, xA.y, c[nt][1]);
                        o2 = p10 * fmaf(-2.0f * aB.x * xB.x, xB.x, c[nt][2]);
                        o3 = p11 * fmaf(-2.0f * aB.y * xB.y, xB.y, c[nt][3]);
                    } else {
                        o0 = p00 * c[nt][0]; o1 = p01 * c[nt][1];
                        o2 = p10 * c[nt][2]; o3 = p11 * c[nt][3];
                    }
                    float* dst = (s == 1) ? st1 : (s == 2) ? st4 : st3;
                    *(float2*)(dst + ra * ST_STRIDE + col0) = make_float2(o0, o1);
                    *(float2*)(dst + rb * ST_STRIDE + col0) = make_float2(o2, o3);
                }
            }
            __syncthreads();
        }

        // ---- layer 4: warp wid reduces rows 2wid, 2wid+1 over all states ----
        {
            float acc[2][4];
            #pragma unroll
            for (int r = 0; r < 2; r++)
                #pragma unroll
                for (int k = 0; k < 4; k++) acc[r][k] = 0.f;
            #pragma unroll
            for (int m = 0; m < 4; m++) {
                const int j = lane + 32 * m;
                const float w4 = __ldg(W4 + j);
                #pragma unroll
                for (int r = 0; r < 2; r++) {
                    const int row = 2 * wid + r;
                    acc[r][0] = fmaf(w4, st0[row * ST_STRIDE + j], acc[r][0]);
                    acc[r][1] = fmaf(w4, st1[row * ST_STRIDE + j], acc[r][1]);
                    acc[r][2] = fmaf(w4, st4[row * ST_STRIDE + j], acc[r][2]);
                    acc[r][3] = fmaf(w4, st3[row * ST_STRIDE + j], acc[r][3]);
                }
            }
            #pragma unroll
            for (int off = 16; off > 0; off >>= 1)
                #pragma unroll
                for (int r = 0; r < 2; r++)
                    #pragma unroll
                    for (int k = 0; k < 4; k++)
                        acc[r][k] += __shfl_down_sync(0xffffffffu, acc[r][k], off);
            if (lane == 0) {
                #pragma unroll
                for (int r = 0; r < 2; r++) {
                    const float u   = acc[r][0] + b4v;
                    const float ut  = acc[r][1];
                    const float ux  = acc[r][2];
                    const float uxx = acc[r][3];
                    out[tile * 32 + 2 * wid + r] =
                        (tile < TEQ) ? (fmaf(u, ux, ut) - NU * uxx) : u;
                }
            }
        }
        __syncthreads();
    }
}

extern "C" void kernel_launch(void* const* d_in, const int* in_sizes, int n_in,
                              void* d_out, int out_size)
{
    const float* tx_eq   = (const float*)d_in[0];
    const float* tx_init = (const float*)d_in[1];
    const float* tx_bnd  = (const float*)d_in[2];
    const float* W0 = (const float*)d_in[3];
    const float* b0 = (const float*)d_in[4];
    const float* W1 = (const float*)d_in[5];
    const float* b1 = (const float*)d_in[6];
    const float* W2 = (const float*)d_in[7];
    const float* b2 = (const float*)d_in[8];
    const float* W3 = (const float*)d_in[9];
    const float* b3 = (const float*)d_in[10];
    const float* W4 = (const float*)d_in[11];
    const float* b4 = (const float*)d_in[12];
    float* out = (float*)d_out;

    prep_kernel<<<48, 256>>>(W1, W2, W3);

    cudaFuncSetAttribute(pinn_mma, cudaFuncAttributeMaxDynamicSharedMemorySize, SMEM_BYTES);
    int sms = 148;
    cudaDeviceGetAttribute(&sms, cudaDevAttrMultiProcessorCount, 0);
    if (sms > NTILES) sms = NTILES;

    pinn_mma<<<sms, 512, SMEM_BYTES>>>(tx_eq, tx_init, tx_bnd,
        W0, b0, b1, b2, b3, W4, b4, out);
}